// round 1
// baseline (speedup 1.0000x reference)
#include <cuda_runtime.h>
#include <cstdint>

#define N_USER 100000
#define N_ITEM 50000
#define N_NODES (N_USER + N_ITEM)
#define EMB 64
#define NNZ 4000000
#define BATCH 4096
#define N_LAYERS 3

// Scratch (static device globals — no allocation in kernel_launch)
__device__ float g_prop[(size_t)N_NODES * EMB];   // 38.4 MB
__device__ int   g_flag[N_NODES];                 // 600 KB

// ---------------------------------------------------------------------------
// Kernel 1: clear flags
// ---------------------------------------------------------------------------
__global__ void k_zero_flags() {
    int i = blockIdx.x * blockDim.x + threadIdx.x;
    if (i < N_NODES) g_flag[i] = 0;
}

// ---------------------------------------------------------------------------
// Kernel 2: mark sampled nodes and zero their prop rows.
// One thread per (sample-row, float4-chunk): 3*BATCH*16 threads.
// Duplicate nodes race only on identical writes (flag=1, prop=0) — benign.
// ---------------------------------------------------------------------------
__global__ void k_mark(const int* __restrict__ users,
                       const int* __restrict__ pos_items,
                       const int* __restrict__ neg_items) {
    int tid = blockIdx.x * blockDim.x + threadIdx.x;
    if (tid >= 3 * BATCH * 16) return;
    int j4   = tid & 15;
    int row  = tid >> 4;          // 0 .. 3*BATCH-1
    int slot = row / BATCH;
    int i    = row % BATCH;
    int node;
    if (slot == 0)      node = users[i];
    else if (slot == 1) node = N_USER + pos_items[i];
    else                node = N_USER + neg_items[i];
    if (j4 == 0) g_flag[node] = 1;
    float4 z = make_float4(0.f, 0.f, 0.f, 0.f);
    reinterpret_cast<float4*>(g_prop + (size_t)node * EMB)[j4] = z;
}

// ---------------------------------------------------------------------------
// Kernel 3: edge scan. One thread per edge; warp cooperates on active edges.
// Active fraction ~8%: ballot + shfl serializes active edges across the warp;
// lanes 0..15 each handle one float4 of the 64-dim row (coalesced gather +
// vector red.global.add.v4.f32 scatter).
// ---------------------------------------------------------------------------
__global__ void k_edges(const int*   __restrict__ rows,
                        const int*   __restrict__ cols,
                        const float* __restrict__ vals,
                        const float* __restrict__ user_emb,
                        const float* __restrict__ item_emb) {
    int e = blockIdx.x * blockDim.x + threadIdx.x;
    int r = 0, c = 0;
    float v = 0.f;
    bool active = false;
    if (e < NNZ) {
        r = rows[e];
        active = (g_flag[r] != 0);
    }
    unsigned mask = __ballot_sync(0xffffffffu, active);
    if (active) {
        c = cols[e];
        v = vals[e];
    }
    int lane = threadIdx.x & 31;
    while (mask) {
        int src = __ffs(mask) - 1;
        mask &= mask - 1;
        int   rr = __shfl_sync(0xffffffffu, r, src);
        int   cc = __shfl_sync(0xffffffffu, c, src);
        float vv = __shfl_sync(0xffffffffu, v, src);
        if (lane < 16) {
            const float* x = (cc < N_USER)
                ? (user_emb + (size_t)cc * EMB)
                : (item_emb + (size_t)(cc - N_USER) * EMB);
            float4 xv = reinterpret_cast<const float4*>(x)[lane];
            float* dst = g_prop + (size_t)rr * EMB + lane * 4;
            unsigned long long gp = __cvta_generic_to_global(dst);
            asm volatile(
                "red.global.add.v4.f32 [%0], {%1, %2, %3, %4};"
                :: "l"(gp), "f"(vv * xv.x), "f"(vv * xv.y),
                   "f"(vv * xv.z), "f"(vv * xv.w)
                : "memory");
        }
    }
}

// ---------------------------------------------------------------------------
// Kernel 4: epilogue gather. out[slot][i][:] = (ego[node] + 3*prop[node]) / 4
// One thread per float4: 3*BATCH*16 threads.
// ---------------------------------------------------------------------------
__global__ void k_gather(const int*   __restrict__ users,
                         const int*   __restrict__ pos_items,
                         const int*   __restrict__ neg_items,
                         const float* __restrict__ user_emb,
                         const float* __restrict__ item_emb,
                         float*       __restrict__ out) {
    int tid = blockIdx.x * blockDim.x + threadIdx.x;
    if (tid >= 3 * BATCH * 16) return;
    int j4   = tid & 15;
    int row  = tid >> 4;
    int slot = row / BATCH;
    int i    = row % BATCH;
    int node;
    if (slot == 0)      node = users[i];
    else if (slot == 1) node = N_USER + pos_items[i];
    else                node = N_USER + neg_items[i];

    const float* x = (node < N_USER)
        ? (user_emb + (size_t)node * EMB)
        : (item_emb + (size_t)(node - N_USER) * EMB);
    float4 xe = reinterpret_cast<const float4*>(x)[j4];
    float4 pr = reinterpret_cast<const float4*>(g_prop + (size_t)node * EMB)[j4];
    const float s = 1.0f / (N_LAYERS + 1);
    float4 o;
    o.x = (xe.x + N_LAYERS * pr.x) * s;
    o.y = (xe.y + N_LAYERS * pr.y) * s;
    o.z = (xe.z + N_LAYERS * pr.z) * s;
    o.w = (xe.w + N_LAYERS * pr.w) * s;
    reinterpret_cast<float4*>(out)[(size_t)row * 16 + j4] = o;
}

// ---------------------------------------------------------------------------
extern "C" void kernel_launch(void* const* d_in, const int* in_sizes, int n_in,
                              void* d_out, int out_size) {
    const int*   adj_rows  = (const int*)  d_in[0];
    const int*   adj_cols  = (const int*)  d_in[1];
    const float* adj_vals  = (const float*)d_in[2];
    const float* user_emb  = (const float*)d_in[3];
    const float* item_emb  = (const float*)d_in[4];
    const int*   users     = (const int*)  d_in[5];
    const int*   pos_items = (const int*)  d_in[6];
    const int*   neg_items = (const int*)  d_in[7];
    float*       out       = (float*)d_out;

    k_zero_flags<<<(N_NODES + 255) / 256, 256>>>();
    k_mark<<<(3 * BATCH * 16 + 255) / 256, 256>>>(users, pos_items, neg_items);
    k_edges<<<NNZ / 256, 256>>>(adj_rows, adj_cols, adj_vals, user_emb, item_emb);
    k_gather<<<(3 * BATCH * 16 + 255) / 256, 256>>>(users, pos_items, neg_items,
                                                    user_emb, item_emb, out);
}

// round 2
// speedup vs baseline: 1.1220x; 1.1220x over previous
#include <cuda_runtime.h>
#include <cstdint>

#define N_USER 100000
#define N_ITEM 50000
#define N_NODES (N_USER + N_ITEM)
#define EMB 64
#define NNZ 4000000
#define BATCH 4096
#define NSAMP (3 * BATCH)          // 12288 sample rows
#define N_LAYERS 3
#define FLAG_INIT 0x7fffffff

// Scratch (static device globals — no allocation in kernel_launch)
__device__ float g_prop[(size_t)NSAMP * EMB];    // 3 MB compact accumulator
__device__ int   g_flag[N_NODES];                // node -> canonical sample row (or FLAG_INIT)

// ---------------------------------------------------------------------------
// Kernel 1: init. Reset flags to FLAG_INIT, zero the compact prop region.
// ---------------------------------------------------------------------------
__global__ void k_init() {
    int i = blockIdx.x * blockDim.x + threadIdx.x;
    if (i < N_NODES) g_flag[i] = FLAG_INIT;
    if (i < NSAMP * (EMB / 4)) {   // 196608 float4 slots
        reinterpret_cast<float4*>(g_prop)[i] = make_float4(0.f, 0.f, 0.f, 0.f);
    }
}

// ---------------------------------------------------------------------------
// Kernel 2: mark. flag[node] = min sample-row index referencing node.
// Deterministic (atomicMin), mostly-unique addresses -> cheap.
// ---------------------------------------------------------------------------
__global__ void k_mark(const int* __restrict__ users,
                       const int* __restrict__ pos_items,
                       const int* __restrict__ neg_items) {
    int row = blockIdx.x * blockDim.x + threadIdx.x;
    if (row >= NSAMP) return;
    int slot = row / BATCH;
    int i    = row % BATCH;
    int node;
    if (slot == 0)      node = users[i];
    else if (slot == 1) node = N_USER + pos_items[i];
    else                node = N_USER + neg_items[i];
    atomicMin(&g_flag[node], row);
}

// ---------------------------------------------------------------------------
// Kernel 3: edge scan + scatter. One thread per edge; warp serializes active
// edges TWO at a time (lanes 0-15 = edge A, lanes 16-31 = edge B).
// Streamed data uses __ldcs to keep embeddings resident in L2 across replays.
// ---------------------------------------------------------------------------
__global__ void k_edges(const int*   __restrict__ rows,
                        const int*   __restrict__ cols,
                        const float* __restrict__ vals,
                        const float* __restrict__ user_emb,
                        const float* __restrict__ item_emb) {
    int e = blockIdx.x * blockDim.x + threadIdx.x;
    int dense = FLAG_INIT, c = 0;
    float v = 0.f;
    if (e < NNZ) {
        int r = __ldcs(rows + e);
        dense = g_flag[r];
    }
    bool active = (dense != FLAG_INIT);
    unsigned mask = __ballot_sync(0xffffffffu, active);
    if (active) {
        c = __ldcs(cols + e);
        v = __ldcs(vals + e);
    }
    int lane = threadIdx.x & 31;
    int half = lane >> 4;          // 0: first edge, 1: second edge
    int j4   = lane & 15;          // float4 chunk within the 64-dim row
    while (mask) {
        int s0 = __ffs(mask) - 1;
        mask &= mask - 1;
        int s1 = 32;               // sentinel: no second edge
        if (mask) {
            s1 = __ffs(mask) - 1;
            mask &= mask - 1;
        }
        int  src  = half ? s1 : s0;
        bool have = (src < 32);
        int  safe = have ? src : 0;
        int   dd = __shfl_sync(0xffffffffu, dense, safe);
        int   cc = __shfl_sync(0xffffffffu, c, safe);
        float vv = __shfl_sync(0xffffffffu, v, safe);
        if (have) {
            const float* x = (cc < N_USER)
                ? (user_emb + (size_t)cc * EMB)
                : (item_emb + (size_t)(cc - N_USER) * EMB);
            float4 xv = reinterpret_cast<const float4*>(x)[j4];
            float* dst = g_prop + (size_t)dd * EMB + j4 * 4;
            unsigned long long gp = __cvta_generic_to_global(dst);
            asm volatile(
                "red.global.add.v4.f32 [%0], {%1, %2, %3, %4};"
                :: "l"(gp), "f"(vv * xv.x), "f"(vv * xv.y),
                   "f"(vv * xv.z), "f"(vv * xv.w)
                : "memory");
        }
    }
}

// ---------------------------------------------------------------------------
// Kernel 4: epilogue gather. out[row][:] = (ego[node] + 3*prop[flag[node]]) / 4
// One thread per float4 chunk: NSAMP*16 threads.
// ---------------------------------------------------------------------------
__global__ void k_gather(const int*   __restrict__ users,
                         const int*   __restrict__ pos_items,
                         const int*   __restrict__ neg_items,
                         const float* __restrict__ user_emb,
                         const float* __restrict__ item_emb,
                         float*       __restrict__ out) {
    int tid = blockIdx.x * blockDim.x + threadIdx.x;
    if (tid >= NSAMP * 16) return;
    int j4   = tid & 15;
    int row  = tid >> 4;
    int slot = row / BATCH;
    int i    = row % BATCH;
    int node;
    if (slot == 0)      node = users[i];
    else if (slot == 1) node = N_USER + pos_items[i];
    else                node = N_USER + neg_items[i];

    int dense = g_flag[node];      // canonical compact row (always < NSAMP here)

    const float* x = (node < N_USER)
        ? (user_emb + (size_t)node * EMB)
        : (item_emb + (size_t)(node - N_USER) * EMB);
    float4 xe = reinterpret_cast<const float4*>(x)[j4];
    float4 pr = reinterpret_cast<const float4*>(g_prop + (size_t)dense * EMB)[j4];
    const float s = 1.0f / (N_LAYERS + 1);
    float4 o;
    o.x = (xe.x + N_LAYERS * pr.x) * s;
    o.y = (xe.y + N_LAYERS * pr.y) * s;
    o.z = (xe.z + N_LAYERS * pr.z) * s;
    o.w = (xe.w + N_LAYERS * pr.w) * s;
    reinterpret_cast<float4*>(out)[(size_t)row * 16 + j4] = o;
}

// ---------------------------------------------------------------------------
extern "C" void kernel_launch(void* const* d_in, const int* in_sizes, int n_in,
                              void* d_out, int out_size) {
    const int*   adj_rows  = (const int*)  d_in[0];
    const int*   adj_cols  = (const int*)  d_in[1];
    const float* adj_vals  = (const float*)d_in[2];
    const float* user_emb  = (const float*)d_in[3];
    const float* item_emb  = (const float*)d_in[4];
    const int*   users     = (const int*)  d_in[5];
    const int*   pos_items = (const int*)  d_in[6];
    const int*   neg_items = (const int*)  d_in[7];
    float*       out       = (float*)d_out;

    const int initN = NSAMP * (EMB / 4) > N_NODES ? NSAMP * (EMB / 4) : N_NODES;
    k_init<<<(initN + 255) / 256, 256>>>();
    k_mark<<<(NSAMP + 255) / 256, 256>>>(users, pos_items, neg_items);
    k_edges<<<NNZ / 256, 256>>>(adj_rows, adj_cols, adj_vals, user_emb, item_emb);
    k_gather<<<(NSAMP * 16 + 255) / 256, 256>>>(users, pos_items, neg_items,
                                                user_emb, item_emb, out);
}